// round 14
// baseline (speedup 1.0000x reference)
#include <cuda_runtime.h>
#include <cuda_bf16.h>
#include <mma.h>
#include <cstdint>
#include <cfloat>

using namespace nvcuda;

// Problem constants
#define MTOK 32768
#define DDIM 256
#define KCB  1024
#define QST  4
#define QUANT_ELEMS (MTOK*DDIM)
#define CB_ELEMS    (QST*KCB*DDIM)
#define IDX_OFF     QUANT_ELEMS
#define LOSS_OFF    (QUANT_ELEMS + QST*MTOK)

#define BM 128                  // tokens per CTA
#define TILE_N 128              // codes per tile
#define NTILES (KCB/TILE_N)     // 8
#define NTHREADS 512
#define SAB 264                 // A16/B16 row stride in bf16 elems (528B, 16B-mult, ldsm conflict-free)
#define SD  132                 // D row stride in floats (528B)

// ---------------- device scratch ----------------
__device__ float          g_res[QUANT_ELEMS];
__device__ __nv_bfloat16  g_cb16[CB_ELEMS];
__device__ float          g_cnorm[QST*KCB];
__device__ int            g_maxcn_i[QST];
__device__ double         g_loss;

__device__ __forceinline__ uint32_t pack2(float lo, float hi) {
    return ((uint32_t)__bfloat16_as_ushort(__float2bfloat16_rn(hi)) << 16)
         | (uint32_t)__bfloat16_as_ushort(__float2bfloat16_rn(lo));
}

// ---------------- init ----------------
__global__ void init_kernel() {
    if (threadIdx.x == 0) g_loss = 0.0;
    if (threadIdx.x < QST) g_maxcn_i[threadIdx.x] = 0;
}

// ---------------- prep: cnorm + bf16 codebook + per-stage max cnorm ----------------
__global__ void prep_kernel(const float* __restrict__ cb) {
    int warp  = blockIdx.x * (blockDim.x >> 5) + (threadIdx.x >> 5);
    int lane  = threadIdx.x & 31;
    int nwarp = gridDim.x * (blockDim.x >> 5);
    for (int row = warp; row < QST*KCB; row += nwarp) {
        const float* p = cb + (size_t)row * DDIM;
        float s = 0.f;
        #pragma unroll
        for (int j = 0; j < DDIM/32; j++) {
            float v = p[j*32 + lane];
            g_cb16[(size_t)row * DDIM + j*32 + lane] = __float2bfloat16_rn(v);
            s = fmaf(v, v, s);
        }
        #pragma unroll
        for (int o = 16; o; o >>= 1) s += __shfl_xor_sync(0xffffffffu, s, o);
        if (lane == 0) {
            g_cnorm[row] = s;
            atomicMax(&g_maxcn_i[row / KCB], __float_as_int(s));  // cnorm > 0
        }
    }
}

// ---------------- main: wmma bf16 screen + exact fp32 rescore ----------------
extern "C" __global__ void __launch_bounds__(NTHREADS)
rvq_wmma_kernel(const float* __restrict__ x, const float* __restrict__ cb,
                float* __restrict__ out) {
    extern __shared__ char dsm[];
    __nv_bfloat16* A16 = (__nv_bfloat16*)dsm;                       // 128*264*2 = 67584 B
    __nv_bfloat16* B16 = (__nv_bfloat16*)(dsm + 67584);             // 67584 B
    float*         Dsm = (float*)(dsm + 135168);                    // 128*132*4 = 67584 B

    __shared__ float s_cn[KCB];
    __shared__ float s_bestA[BM];
    __shared__ int   s_idx[BM];
    __shared__ float s_rnorm[BM];
    __shared__ float s_part[4*BM];
    __shared__ float s_wsum[NTHREADS/32];

    const int tid = threadIdx.x;
    const int wid = tid >> 5;
    const int tokbase = blockIdx.x * BM;

    // update/rnorm mapping (validated structure): 4 threads per token
    const int utok = tid >> 2;
    const int ug   = tid & 3;

    // screen mapping: 4 consecutive lanes per token (shfl-combinable)
    const int stok = tid >> 2;
    const int q4   = tid & 3;

    // wmma warp tiling: 4x4 grid of 32x32 blocks
    const int mrow2 = (wid & 3) * 32;
    const int ncol2 = (wid >> 2) * 32;

    // ---- initial rnorm (same reduction order as validated kernel) ----
    {
        const float4* rr = (const float4*)(g_res + (size_t)(tokbase + utok) * DDIM) + ug*16;
        float partial = 0.f;
        #pragma unroll
        for (int j = 0; j < 16; j++) {
            float4 r = rr[j];
            partial = fmaf(r.x, r.x, partial);
            partial = fmaf(r.y, r.y, partial);
            partial = fmaf(r.z, r.z, partial);
            partial = fmaf(r.w, r.w, partial);
        }
        s_part[ug*BM + utok] = partial;
        __syncthreads();
        if (tid < BM) {
            s_rnorm[tid] = ((s_part[0*BM + tid] + s_part[1*BM + tid])
                          + (s_part[2*BM + tid] + s_part[3*BM + tid]));
        }
        __syncthreads();
    }

    for (int q = 0; q < QST; q++) {
        const float* cbq = cb + (size_t)q * KCB * DDIM;

        // stage cnorms into smem; init bestA
        for (int i = tid; i < KCB; i += NTHREADS) s_cn[i] = g_cnorm[q*KCB + i];
        if (tid < BM) s_bestA[tid] = FLT_MAX;

        // ---- A16: residual -> bf16 row-major [128 x 256], stride 264 ----
        {
            const int tc = tid & 127;       // token
            const int ch = tid >> 7;        // 0..3, 64 dims each
            const float4* rr = (const float4*)(g_res + (size_t)(tokbase + tc) * DDIM + ch*64);
            uint4* dst = (uint4*)(A16 + tc*SAB + ch*64);
            #pragma unroll
            for (int jj = 0; jj < 8; jj++) {
                float4 v0 = rr[2*jj], v1 = rr[2*jj+1];
                uint4 u;
                u.x = pack2(v0.x, v0.y);
                u.y = pack2(v0.z, v0.w);
                u.z = pack2(v1.x, v1.y);
                u.w = pack2(v1.z, v1.w);
                dst[jj] = u;
            }
        }
        __syncthreads();

        // per-thread screen state
        const float rn = s_rnorm[stok];
        const float mcn = __int_as_float(g_maxcn_i[q]);
        const float margin = 0.04f * sqrtf(rn * mcn) + 0.02f;   // >= 2x provable bf16 bound
        float bestE = FLT_MAX;
        int   bidx  = 0;

        for (int tile = 0; tile < NTILES; tile++) {
            // ---- B16: 128 codes x 256 dims bf16 tile ----
            {
                const int code = tid & 127;
                const int part = tid >> 7;
                const uint4* src = (const uint4*)(g_cb16
                    + ((size_t)(q*KCB + tile*TILE_N + code)) * DDIM + part*64);
                uint4* dst = (uint4*)(B16 + code*SAB + part*64);
                #pragma unroll
                for (int j = 0; j < 8; j++) dst[j] = src[j];
            }
            __syncthreads();

            // ---- wmma: D[128x128] = A (row) x B^T (codebook rows = col-major k x n) ----
            {
                wmma::fragment<wmma::accumulator, 16,16,16, float> acc[2][2];
                #pragma unroll
                for (int i = 0; i < 2; i++)
                    #pragma unroll
                    for (int j = 0; j < 2; j++) wmma::fill_fragment(acc[i][j], 0.0f);

                #pragma unroll 4
                for (int kk = 0; kk < DDIM; kk += 16) {
                    wmma::fragment<wmma::matrix_a, 16,16,16, __nv_bfloat16, wmma::row_major> af[2];
                    wmma::fragment<wmma::matrix_b, 16,16,16, __nv_bfloat16, wmma::col_major> bf[2];
                    wmma::load_matrix_sync(af[0], A16 + (mrow2     )*SAB + kk, SAB);
                    wmma::load_matrix_sync(af[1], A16 + (mrow2 + 16)*SAB + kk, SAB);
                    wmma::load_matrix_sync(bf[0], B16 + (ncol2     )*SAB + kk, SAB);
                    wmma::load_matrix_sync(bf[1], B16 + (ncol2 + 16)*SAB + kk, SAB);
                    wmma::mma_sync(acc[0][0], af[0], bf[0], acc[0][0]);
                    wmma::mma_sync(acc[0][1], af[0], bf[1], acc[0][1]);
                    wmma::mma_sync(acc[1][0], af[1], bf[0], acc[1][0]);
                    wmma::mma_sync(acc[1][1], af[1], bf[1], acc[1][1]);
                }
                #pragma unroll
                for (int i = 0; i < 2; i++)
                    #pragma unroll
                    for (int j = 0; j < 2; j++)
                        wmma::store_matrix_sync(Dsm + (mrow2 + 16*i)*SD + ncol2 + 16*j,
                                                acc[i][j], SD, wmma::mem_row_major);
            }
            __syncthreads();

            // ---- screen: pass1 tile-min, pass2 margin rescore ----
            {
                const int cbase = tile * TILE_N;
                float mymin = FLT_MAX;
                #pragma unroll 8
                for (int jj = 0; jj < 32; jj++) {
                    int c = q4 + 4*jj;
                    float approx = __fsub_rn(s_cn[cbase + c],
                                             __fmul_rn(2.0f, Dsm[stok*SD + c]));
                    mymin = fminf(mymin, approx);
                }
                mymin = fminf(mymin, __shfl_xor_sync(0xffffffffu, mymin, 1));
                mymin = fminf(mymin, __shfl_xor_sync(0xffffffffu, mymin, 2));
                float nb = fminf(s_bestA[stok], mymin);
                if (q4 == 0) s_bestA[stok] = nb;
                float thr = nb + margin;

                #pragma unroll 8
                for (int jj = 0; jj < 32; jj++) {
                    int c = q4 + 4*jj;
                    float approx = __fsub_rn(s_cn[cbase + c],
                                             __fmul_rn(2.0f, Dsm[stok*SD + c]));
                    if (approx <= thr) {
                        int code = cbase + c;
                        // exact fp32 rescore — summation order identical to validated kernel
                        const float4* rr = (const float4*)(g_res + (size_t)(tokbase + stok) * DDIM);
                        const float4* cc = (const float4*)(cbq + (size_t)code * DDIM);
                        float aL = 0.f, aH = 0.f;
                        #pragma unroll 8
                        for (int i = 0; i < 32; i++) {
                            float4 r = rr[i], cv = cc[i];
                            aL = fmaf(r.x, cv.x, aL); aL = fmaf(r.y, cv.y, aL);
                            aL = fmaf(r.z, cv.z, aL); aL = fmaf(r.w, cv.w, aL);
                        }
                        #pragma unroll 8
                        for (int i = 32; i < 64; i++) {
                            float4 r = rr[i], cv = cc[i];
                            aH = fmaf(r.x, cv.x, aH); aH = fmaf(r.y, cv.y, aH);
                            aH = fmaf(r.z, cv.z, aH); aH = fmaf(r.w, cv.w, aH);
                        }
                        float dotx = __fadd_rn(aL, aH);
                        float sc = __fadd_rn(__fsub_rn(rn, __fmul_rn(2.0f, dotx)),
                                             s_cn[code]);
                        if (sc < bestE || (sc == bestE && code < bidx)) { bestE = sc; bidx = code; }
                    }
                }
            }
            __syncthreads();   // D + B16 reusable
        }

        // ---- combine 4 lanes per token (min, index tiebreak) ----
        {
            #pragma unroll
            for (int o = 1; o < 4; o <<= 1) {
                float ov = __shfl_xor_sync(0xffffffffu, bestE, o);
                int   oi = __shfl_xor_sync(0xffffffffu, bidx,  o);
                if (ov < bestE || (ov == bestE && oi < bidx)) { bestE = ov; bidx = oi; }
            }
            if (q4 == 0) {
                s_idx[stok] = bidx;
                out[IDX_OFF + q*MTOK + tokbase + stok] = (float)bidx;
            }
        }
        __syncthreads();

        // ---- update: residual -= codeword (global), loss + new rnorm ----
        {
            const int idx = s_idx[utok];
            float4* rrow = (float4*)(g_res + (size_t)(tokbase + utok) * DDIM) + ug*16;
            const float4* crow = (const float4*)(cbq + (size_t)idx * DDIM) + ug*16;
            float partial = 0.f;
            #pragma unroll
            for (int j = 0; j < 16; j++) {
                float4 r = rrow[j], c = crow[j];
                r.x -= c.x; r.y -= c.y; r.z -= c.z; r.w -= c.w;
                rrow[j] = r;
                partial = fmaf(r.x, r.x, partial);
                partial = fmaf(r.y, r.y, partial);
                partial = fmaf(r.z, r.z, partial);
                partial = fmaf(r.w, r.w, partial);
            }
            s_part[ug*BM + utok] = partial;
            __syncthreads();

            float myr = 0.f;
            if (tid < BM) {
                myr = ((s_part[0*BM + tid] + s_part[1*BM + tid])
                     + (s_part[2*BM + tid] + s_part[3*BM + tid]));
                s_rnorm[tid] = myr;
            }
            #pragma unroll
            for (int o = 16; o; o >>= 1)
                myr += __shfl_xor_sync(0xffffffffu, myr, o);
            if (tid < BM && (tid & 31) == 0) s_wsum[tid >> 5] = myr;
            __syncthreads();
            if (tid == 0) {
                float tot = ((s_wsum[0] + s_wsum[1]) + (s_wsum[2] + s_wsum[3]));
                atomicAdd(&g_loss, (double)tot);
            }
        }
        __syncthreads();
    }

    // ---- epilogue: quant = x - residual_final ----
    {
        const float4* xr = (const float4*)(x + (size_t)(tokbase + utok) * DDIM) + ug*16;
        const float4* rr = (const float4*)(g_res + (size_t)(tokbase + utok) * DDIM) + ug*16;
        float4* orow = (float4*)(out + (size_t)(tokbase + utok) * DDIM) + ug*16;
        #pragma unroll
        for (int j = 0; j < 16; j++) {
            float4 a = xr[j], b = rr[j];
            a.x -= b.x; a.y -= b.y; a.z -= b.z; a.w -= b.w;
            orow[j] = a;
        }
    }
}

// ---------------- loss epilogue ----------------
__global__ void loss_kernel(float* __restrict__ out) {
    if (threadIdx.x < QST) {
        float loss = (float)(1.25 * g_loss / (double)QUANT_ELEMS);
        out[LOSS_OFF + threadIdx.x] = loss;
    }
}

// ---------------- launch ----------------
extern "C" void kernel_launch(void* const* d_in, const int* in_sizes, int n_in,
                              void* d_out, int out_size) {
    const float* x  = (const float*)d_in[0];
    const float* cb = (const float*)d_in[1];
    if (n_in >= 2 && in_sizes[0] == CB_ELEMS && in_sizes[1] == QUANT_ELEMS) {
        x  = (const float*)d_in[1];
        cb = (const float*)d_in[0];
    }
    float* out = (float*)d_out;

    void* resptr = nullptr;
    cudaGetSymbolAddress(&resptr, g_res);
    cudaMemcpyAsync(resptr, x, sizeof(float)*QUANT_ELEMS, cudaMemcpyDeviceToDevice);

    const int smem_bytes = 67584 * 3;   // A16 + B16 + D = 202752
    cudaFuncSetAttribute((const void*)rvq_wmma_kernel,
                         cudaFuncAttributeMaxDynamicSharedMemorySize, smem_bytes);

    init_kernel<<<1, 32>>>();
    prep_kernel<<<148, 256>>>(cb);
    rvq_wmma_kernel<<<MTOK/BM, NTHREADS, smem_bytes>>>(x, cb, out);
    loss_kernel<<<1, 32>>>(out);
}